// round 1
// baseline (speedup 1.0000x reference)
#include <cuda_runtime.h>
#include <math.h>

// ---------------- problem constants ----------------
#define Bsz   64
#define Nn    200      // seq len == state dim
#define Dd    200
#define Mm    50
#define Lb    512
#define Hb    768
#define NUMQ  10000
#define BT    (Bsz*Nn)          // 12800
#define MV_PER_B 2010000L       // 201*50*200
#define OUT_P_SIZE   12800L
#define OUT_MV_SIZE  128640000L
#define OUT_W_SIZE   640000L

// ---------------- scratch (static device globals; no runtime alloc) ----------------
__device__ float g_em  [ (long)Bsz*Lb*Dd ];   // [64,512,200]  em = bert@W_at.T+b
__device__ float g_VE  [ (long)BT*400 ];      // [b,n, 0:200]=v, [200:400]=em_at row
__device__ float g_RK  [ (long)BT*400 ];      // [b,n, 0:200]=read, [200:400]=k
__device__ float g_e   [ (long)BT*Dd ];
__device__ float g_a   [ (long)BT*Dd ];
__device__ float g_f   [ (long)BT*Dd ];
__device__ float g_fl  [ (long)BT*Dd ];       // f_l_pre [b, i, j] row-major
__device__ float g_wlog[ (long)BT*Mm ];

// ---------------- generic tiled fp32 GEMM: C = act(A @ B^T + bias) ----------------
// A[m,k] = A[m*lda_row + k*lda_k]  (TRANS_A picks the coalesced load mapping)
// B is [N,K] row-major (weight layout). Optional batching via blockIdx.z strides.
// ACT: 0 none, 1 sigmoid, 2 tanh, 3 relu
template<int ACT, bool TRANS_A>
__global__ void gemm_bias_act(const float* __restrict__ A, const float* __restrict__ B,
                              const float* __restrict__ bias, float* __restrict__ C,
                              int M, int N, int K,
                              long sAb, long sCb,
                              int lda_row, int lda_k, int ldc)
{
    __shared__ float As[16][64];
    __shared__ float Bs[16][64];
    A += (long)blockIdx.z * sAb;
    C += (long)blockIdx.z * sCb;
    const int tid = threadIdx.x;
    const int tx = tid & 15, ty = tid >> 4;
    const int m0 = blockIdx.y * 64, n0 = blockIdx.x * 64;
    float acc[4][4] = {};

    for (int k0 = 0; k0 < K; k0 += 16) {
        #pragma unroll
        for (int u = 0; u < 4; u++) {
            int li = tid * 4 + u;
            int kl, ml;
            if (TRANS_A) { kl = li >> 6; ml = li & 63; }   // contiguous m
            else         { kl = li & 15; ml = li >> 4; }   // contiguous k
            int m = m0 + ml, k = k0 + kl;
            As[kl][ml] = (m < M && k < K) ? A[(long)m * lda_row + (long)k * lda_k] : 0.f;
        }
        #pragma unroll
        for (int u = 0; u < 4; u++) {
            int li = tid * 4 + u;
            int kl = li & 15, nl = li >> 4;
            int n = n0 + nl, k = k0 + kl;
            Bs[kl][nl] = (n < N && k < K) ? B[(long)n * K + k] : 0.f;
        }
        __syncthreads();
        #pragma unroll
        for (int k = 0; k < 16; k++) {
            float4 av = *(const float4*)&As[k][ty * 4];
            float4 bv = *(const float4*)&Bs[k][tx * 4];
            float a4[4] = {av.x, av.y, av.z, av.w};
            float b4[4] = {bv.x, bv.y, bv.z, bv.w};
            #pragma unroll
            for (int i = 0; i < 4; i++)
                #pragma unroll
                for (int j = 0; j < 4; j++)
                    acc[i][j] += a4[i] * b4[j];
        }
        __syncthreads();
    }
    #pragma unroll
    for (int i = 0; i < 4; i++) {
        int m = m0 + ty * 4 + i;
        if (m >= M) continue;
        #pragma unroll
        for (int j = 0; j < 4; j++) {
            int n = n0 + tx * 4 + j;
            if (n >= N) continue;
            float v = acc[i][j] + (bias ? bias[n] : 0.f);
            if (ACT == 1)      v = 1.f / (1.f + expf(-v));
            else if (ACT == 2) v = tanhf(v);
            else if (ACT == 3) v = fmaxf(v, 0.f);
            C[(long)m * ldc + n] = v;
        }
    }
}

// ---------------- embedding gather: k -> RK[...,200:400], v -> VE[...,0:200] ----------------
__global__ void gather_kernel(const int* __restrict__ q, const int* __restrict__ r,
                              const float* __restrict__ k_emb, const float* __restrict__ v_emb,
                              float* __restrict__ RK, float* __restrict__ VE)
{
    int bt = blockIdx.x;
    int j  = threadIdx.x;
    int qv = q[bt];
    int xv = qv + NUMQ * r[bt];
    if (j < Dd) {
        RK[(long)bt * 400 + 200 + j] = k_emb[(long)qv * Dd + j];
        VE[(long)bt * 400 + j]       = v_emb[(long)xv * Dd + j];
    }
}

// ---------------- row softmax over 50 ----------------
__global__ void softmax50_kernel(const float* __restrict__ lg, float* __restrict__ wout)
{
    int row = blockIdx.x * blockDim.x + threadIdx.x;
    if (row >= BT) return;
    const float* x = lg + (long)row * Mm;
    float e[Mm];
    float mx = -3.4e38f;
    #pragma unroll
    for (int s = 0; s < Mm; s++) { e[s] = x[s]; mx = fmaxf(mx, e[s]); }
    float sum = 0.f;
    #pragma unroll
    for (int s = 0; s < Mm; s++) { e[s] = expf(e[s] - mx); sum += e[s]; }
    float inv = 1.f / sum;
    float* o = wout + (long)row * Mm;
    #pragma unroll
    for (int s = 0; s < Mm; s++) o[s] = e[s] * inv;
}

// ---------------- memory scan: Mv recurrence + read einsum ----------------
// One thread per d-column (chunked 50/block); 50 s-states in registers.
// Emits Mv_pre (coalesced across d per s-row), read -> RK[...,0:200], final state at t=n.
__global__ void scan_kernel(const float* __restrict__ w, const float* __restrict__ e,
                            const float* __restrict__ a, const float* __restrict__ Mv0,
                            float* __restrict__ MvOut, float* __restrict__ RK)
{
    int b = blockIdx.x;
    int d = blockIdx.y * 50 + threadIdx.x;
    bool active = (threadIdx.x < 50);
    __shared__ float ws[Mm];
    float mv[Mm];
    if (active) {
        #pragma unroll
        for (int s = 0; s < Mm; s++) mv[s] = Mv0[s * Dd + d];
    }
    const float* wb = w + (long)b * Nn * Mm;
    const float* eb = e + (long)b * Nn * Dd;
    const float* ab = a + (long)b * Nn * Dd;
    float* mb = MvOut + (long)b * MV_PER_B;
    float* rb = RK + (long)b * Nn * 400;

    for (int t = 0; t < Nn; t++) {
        if (threadIdx.x < Mm) ws[threadIdx.x] = wb[t * Mm + threadIdx.x];
        __syncthreads();
        if (active) {
            float ed = eb[t * Dd + d];
            float ad = ab[t * Dd + d];
            float* mp = mb + (long)t * (Mm * Dd) + d;
            float rd = 0.f;
            #pragma unroll
            for (int s = 0; s < Mm; s++) {
                float m_ = mv[s];
                mp[s * Dd] = m_;               // Mv_pre emit
                float wv = ws[s];
                rd += wv * m_;                 // read einsum
                mv[s] = m_ + wv * (ad - ed * m_);  // = m(1-we)+wa
            }
            rb[t * 400 + d] = rd;
        }
        __syncthreads();
    }
    if (active) {
        float* mp = mb + (long)Nn * (Mm * Dd) + d; // Mv_last slot
        #pragma unroll
        for (int s = 0; s < Mm; s++) mp[s * Dd] = mv[s];
    }
}

// ---------------- final projection p = sigmoid([f | f_l] . Wp + bp) ----------------
// f_l[b,t,i] = f_l_pre[b,i,t]  (transpose folded into the reduction)
__global__ void p_kernel(const float* __restrict__ f, const float* __restrict__ fl,
                         const float* __restrict__ Wp, const float* __restrict__ bp,
                         float* __restrict__ outp)
{
    int b = blockIdx.x;
    __shared__ float wsh[400];
    for (int i = threadIdx.x; i < 400; i += blockDim.x) wsh[i] = Wp[i];
    __syncthreads();
    int t = threadIdx.x;
    if (t < Nn) {
        float acc = bp[0];
        const float* flb = fl + (long)b * Nn * Dd;
        for (int i = 0; i < Nn; i++)          // coalesced across threads t
            acc += flb[(long)i * Dd + t] * wsh[200 + i];
        const float* fb = f + ((long)b * Nn + t) * Dd;
        for (int d = 0; d < Dd; d++)
            acc += fb[d] * wsh[d];
        outp[b * Nn + t] = 1.f / (1.f + expf(-acc));
    }
}

// ---------------- host ----------------
extern "C" void kernel_launch(void* const* d_in, const int* in_sizes, int n_in,
                              void* d_out, int out_size)
{
    const int*   q      = (const int*)  d_in[0];
    const int*   r      = (const int*)  d_in[1];
    const float* bert   = (const float*)d_in[2];
    const float* k_emb  = (const float*)d_in[3];
    const float* v_emb  = (const float*)d_in[4];
    const float* Mk     = (const float*)d_in[5];
    const float* Mv0    = (const float*)d_in[6];
    const float* W_at   = (const float*)d_in[7];
    const float* b_at   = (const float*)d_in[8];
    const float* W_at2  = (const float*)d_in[9];
    const float* b_at2  = (const float*)d_in[10];
    const float* W_fus  = (const float*)d_in[11];
    const float* b_fus  = (const float*)d_in[12];
    const float* W_e    = (const float*)d_in[13];
    const float* b_e    = (const float*)d_in[14];
    const float* W_a    = (const float*)d_in[15];
    const float* b_a    = (const float*)d_in[16];
    const float* W_f    = (const float*)d_in[17];
    const float* b_f    = (const float*)d_in[18];
    const float* W_p    = (const float*)d_in[19];
    const float* b_p    = (const float*)d_in[20];

    float* outp  = (float*)d_out;
    float* outMv = outp + OUT_P_SIZE;
    float* outw  = outMv + OUT_MV_SIZE;

    float *em, *VE, *RK, *e_s, *a_s, *f_s, *fl_s, *wlog;
    cudaGetSymbolAddress((void**)&em,   g_em);
    cudaGetSymbolAddress((void**)&VE,   g_VE);
    cudaGetSymbolAddress((void**)&RK,   g_RK);
    cudaGetSymbolAddress((void**)&e_s,  g_e);
    cudaGetSymbolAddress((void**)&a_s,  g_a);
    cudaGetSymbolAddress((void**)&f_s,  g_f);
    cudaGetSymbolAddress((void**)&fl_s, g_fl);
    cudaGetSymbolAddress((void**)&wlog, g_wlog);

    // 1. gather k,v into concat buffers
    gather_kernel<<<BT, 256>>>(q, r, k_emb, v_emb, RK, VE);

    // 2. em = bert @ W_at.T + b_at       [32768,768] x [200,768]
    gemm_bias_act<0,false><<<dim3(4, 512, 1), 256>>>(
        bert, W_at, b_at, em, Bsz*Lb, Dd, Hb, 0, 0, Hb, 1, Dd);

    // 3. em_at[b] = em[b]^T @ W_at2.T + b_at2  -> VE[...,200:400]   (batched, A transposed)
    gemm_bias_act<0,true><<<dim3(4, 4, Bsz), 256>>>(
        em, W_at2, b_at2, VE + 200, Dd, Dd, Lb,
        (long)Lb * Dd, (long)Nn * 400, 1, Dd, 400);

    // 4. w logits = k @ Mk.T   [12800,200] x [50,200]
    gemm_bias_act<0,false><<<dim3(1, 200, 1), 256>>>(
        RK + 200, Mk, (const float*)nullptr, wlog, BT, Mm, Dd, 0, 0, 400, 1, Mm);

    // 5. softmax -> w output
    softmax50_kernel<<<100, 128>>>(wlog, outw);

    // 6/7. e = sigmoid(v@W_e.T+b), a = tanh(v@W_a.T+b)
    gemm_bias_act<1,false><<<dim3(4, 200, 1), 256>>>(
        VE, W_e, b_e, e_s, BT, Dd, Dd, 0, 0, 400, 1, Dd);
    gemm_bias_act<2,false><<<dim3(4, 200, 1), 256>>>(
        VE, W_a, b_a, a_s, BT, Dd, Dd, 0, 0, 400, 1, Dd);

    // 8. memory scan: Mv output + read -> RK[...,0:200]
    scan_kernel<<<dim3(Bsz, 4, 1), 64>>>(outw, e_s, a_s, Mv0, outMv, RK);

    // 9. f = tanh([read|k] @ W_f.T + b_f)
    gemm_bias_act<2,false><<<dim3(4, 200, 1), 256>>>(
        RK, W_f, b_f, f_s, BT, Dd, 400, 0, 0, 400, 1, Dd);

    // 10. f_l_pre = relu([v|em_at] @ W_fus.T + b_fus)
    gemm_bias_act<3,false><<<dim3(4, 200, 1), 256>>>(
        VE, W_fus, b_fus, fl_s, BT, Dd, 400, 0, 0, 400, 1, Dd);

    // 11. p
    p_kernel<<<Bsz, 256>>>(f_s, fl_s, W_p, b_p, outp);
}

// round 2
// speedup vs baseline: 1.3729x; 1.3729x over previous
#include <cuda_runtime.h>
#include <math.h>

// ---------------- problem constants ----------------
#define Bsz   64
#define Nn    200      // seq len == state dim
#define Dd    200
#define Mm    50
#define Lb    512
#define Hb    768
#define NUMQ  10000
#define BT    (Bsz*Nn)          // 12800
#define MV_PER_B 2010000L       // 201*50*200
#define OUT_P_SIZE   12800L
#define OUT_MV_SIZE  128640000L
#define OUT_W_SIZE   640000L

typedef unsigned long long ull;

// ---------------- scratch (static device globals; no runtime alloc) ----------------
__device__ float g_em  [ (long)Bsz*Lb*Dd ];   // [64,512,200]  em = bert@W_at.T+b
__device__ float g_VE  [ (long)BT*400 ];      // [b,n, 0:200]=v, [200:400]=em_at row
__device__ float g_RK  [ (long)BT*400 ];      // [b,n, 0:200]=read, [200:400]=k
__device__ float g_e   [ (long)BT*Dd ];
__device__ float g_a   [ (long)BT*Dd ];
__device__ float g_f   [ (long)BT*Dd ];
__device__ float g_fl  [ (long)BT*Dd ];       // f_l_pre [b, i, j] row-major
__device__ float g_wlog[ (long)BT*Mm ];

// ---------------- packed f32x2 helpers (FFMA2 path: 2x fp32 FMA rate) ----------------
__device__ __forceinline__ ull dup2(float x) {
    ull r; asm("mov.b64 %0, {%1, %1};" : "=l"(r) : "f"(x)); return r;
}
__device__ __forceinline__ void fma2(ull& d, ull a, ull b) {
    asm("fma.rn.f32x2 %0, %1, %2, %0;" : "+l"(d) : "l"(a), "l"(b));
}
__device__ __forceinline__ float2 unpk2(ull v) {
    float2 f; asm("mov.b64 {%0, %1}, %2;" : "=f"(f.x), "=f"(f.y) : "l"(v)); return f;
}

// ---------------- tiled fp32x2 GEMM: C = act(A @ B^T + bias) ----------------
// Block tile 128(M) x 64(N), K-step 16, 256 threads, 8Mx4N per thread.
// A element = A[m*lda_row + k*lda_k]; TRANS_A selects coalesced load path.
// B is [N,K] row-major. Batched via blockIdx.z (strides sAb/sCb).
// ACT: 0 none, 1 sigmoid, 2 tanh, 3 relu
template<int ACT, bool TRANS_A>
__global__ __launch_bounds__(256)
void gemm2(const float* __restrict__ A, const float* __restrict__ B,
           const float* __restrict__ bias, float* __restrict__ C,
           int M, int N, int K, long sAb, long sCb,
           int lda_row, int lda_k, int ldc)
{
    __shared__ float As[16][128];   // [k][m]
    __shared__ float Bs[16][64];    // [k][n]
    A += (long)blockIdx.z * sAb;
    C += (long)blockIdx.z * sCb;
    const int tid = threadIdx.x;
    const int tx = tid & 15;        // N dir: 4 cols each
    const int ty = tid >> 4;        // M dir: 8 rows each
    const int m0 = blockIdx.y * 128, n0 = blockIdx.x * 64;

    ull acc[4][4] = {};             // [m-pair][n]; pair = (2mp, 2mp+1)

    for (int k0 = 0; k0 < K; k0 += 16) {
        const bool ktail = (k0 + 16 > K);
        // ---- load A tile (2048 floats) ----
        if (!TRANS_A) {
            #pragma unroll
            for (int u = 0; u < 2; u++) {
                int f4  = tid + u * 256;           // 512 float4 slots
                int row = f4 >> 2, kq = (f4 & 3) * 4;
                int m = m0 + row;
                float4 v = make_float4(0.f, 0.f, 0.f, 0.f);
                if (m < M) {
                    if (!ktail) {
                        v = *(const float4*)&A[(long)m * lda_row + k0 + kq];
                    } else {
                        float t4[4];
                        #pragma unroll
                        for (int j = 0; j < 4; j++) {
                            int k = k0 + kq + j;
                            t4[j] = (k < K) ? A[(long)m * lda_row + k] : 0.f;
                        }
                        v = make_float4(t4[0], t4[1], t4[2], t4[3]);
                    }
                }
                As[kq + 0][row] = v.x; As[kq + 1][row] = v.y;
                As[kq + 2][row] = v.z; As[kq + 3][row] = v.w;
            }
        } else {
            #pragma unroll
            for (int u = 0; u < 8; u++) {
                int idx = tid + u * 256;
                int kl = idx >> 7, ml = idx & 127;
                int m = m0 + ml, k = k0 + kl;
                As[kl][ml] = (m < M && k < K)
                    ? A[(long)m * lda_row + (long)k * lda_k] : 0.f;
            }
        }
        // ---- load B tile (1024 floats, 1 float4/thread) ----
        {
            int n = tid >> 2, kq = (tid & 3) * 4;
            int nn = n0 + n;
            float4 v = make_float4(0.f, 0.f, 0.f, 0.f);
            if (nn < N) {
                if (!ktail) {
                    v = *(const float4*)&B[(long)nn * K + k0 + kq];
                } else {
                    float t4[4];
                    #pragma unroll
                    for (int j = 0; j < 4; j++) {
                        int k = k0 + kq + j;
                        t4[j] = (k < K) ? B[(long)nn * K + k] : 0.f;
                    }
                    v = make_float4(t4[0], t4[1], t4[2], t4[3]);
                }
            }
            Bs[kq + 0][n] = v.x; Bs[kq + 1][n] = v.y;
            Bs[kq + 2][n] = v.z; Bs[kq + 3][n] = v.w;
        }
        __syncthreads();
        // ---- compute ----
        #pragma unroll
        for (int k = 0; k < 16; k++) {
            const ull* ap = (const ull*)&As[k][ty * 8];   // 4 M-pairs (8B aligned)
            ull a0 = ap[0], a1 = ap[1], a2 = ap[2], a3 = ap[3];
            float4 bv = *(const float4*)&Bs[k][tx * 4];
            ull b0 = dup2(bv.x), b1 = dup2(bv.y), b2 = dup2(bv.z), b3 = dup2(bv.w);
            fma2(acc[0][0], a0, b0); fma2(acc[0][1], a0, b1);
            fma2(acc[0][2], a0, b2); fma2(acc[0][3], a0, b3);
            fma2(acc[1][0], a1, b0); fma2(acc[1][1], a1, b1);
            fma2(acc[1][2], a1, b2); fma2(acc[1][3], a1, b3);
            fma2(acc[2][0], a2, b0); fma2(acc[2][1], a2, b1);
            fma2(acc[2][2], a2, b2); fma2(acc[2][3], a2, b3);
            fma2(acc[3][0], a3, b0); fma2(acc[3][1], a3, b1);
            fma2(acc[3][2], a3, b2); fma2(acc[3][3], a3, b3);
        }
        __syncthreads();
    }
    // ---- epilogue ----
    #pragma unroll
    for (int mp = 0; mp < 4; mp++) {
        int m = m0 + ty * 8 + mp * 2;
        #pragma unroll
        for (int j = 0; j < 4; j++) {
            int n = n0 + tx * 4 + j;
            if (n >= N) continue;
            float2 c2 = unpk2(acc[mp][j]);
            float bb = bias ? bias[n] : 0.f;
            float v0 = c2.x + bb, v1 = c2.y + bb;
            if (ACT == 1) { v0 = 1.f / (1.f + expf(-v0)); v1 = 1.f / (1.f + expf(-v1)); }
            else if (ACT == 2) { v0 = tanhf(v0); v1 = tanhf(v1); }
            else if (ACT == 3) { v0 = fmaxf(v0, 0.f); v1 = fmaxf(v1, 0.f); }
            if (m     < M) C[(long)(m    ) * ldc + n] = v0;
            if (m + 1 < M) C[(long)(m + 1) * ldc + n] = v1;
        }
    }
}

// ---------------- embedding gather (vectorized float4) ----------------
__global__ void gather_kernel(const int* __restrict__ q, const int* __restrict__ r,
                              const float* __restrict__ k_emb, const float* __restrict__ v_emb,
                              float* __restrict__ RK, float* __restrict__ VE)
{
    int bt = blockIdx.x;
    int j  = threadIdx.x;           // 0..63, active < 50 (float4 lanes)
    if (j >= 50) return;
    int qv = q[bt];
    int xv = qv + NUMQ * r[bt];
    float4 kv = ((const float4*)(k_emb + (long)qv * Dd))[j];
    float4 vv = ((const float4*)(v_emb + (long)xv * Dd))[j];
    ((float4*)(RK + (long)bt * 400 + 200))[j] = kv;
    ((float4*)(VE + (long)bt * 400))[j]       = vv;
}

// ---------------- row softmax over 50 ----------------
__global__ void softmax50_kernel(const float* __restrict__ lg, float* __restrict__ wout)
{
    int row = blockIdx.x * blockDim.x + threadIdx.x;
    if (row >= BT) return;
    const float* x = lg + (long)row * Mm;
    float e[Mm];
    float mx = -3.4e38f;
    #pragma unroll
    for (int s = 0; s < Mm; s++) { e[s] = x[s]; mx = fmaxf(mx, e[s]); }
    float sum = 0.f;
    #pragma unroll
    for (int s = 0; s < Mm; s++) { e[s] = expf(e[s] - mx); sum += e[s]; }
    float inv = 1.f / sum;
    float* o = wout + (long)row * Mm;
    #pragma unroll
    for (int s = 0; s < Mm; s++) o[s] = e[s] * inv;
}

// ---------------- memory scan: Mv recurrence + read einsum ----------------
__global__ void scan_kernel(const float* __restrict__ w, const float* __restrict__ e,
                            const float* __restrict__ a, const float* __restrict__ Mv0,
                            float* __restrict__ MvOut, float* __restrict__ RK)
{
    int b = blockIdx.x;
    int d = blockIdx.y * 50 + threadIdx.x;
    bool active = (threadIdx.x < 50);
    __shared__ float ws[Mm];
    float mv[Mm];
    if (active) {
        #pragma unroll
        for (int s = 0; s < Mm; s++) mv[s] = Mv0[s * Dd + d];
    }
    const float* wb = w + (long)b * Nn * Mm;
    const float* eb = e + (long)b * Nn * Dd;
    const float* ab = a + (long)b * Nn * Dd;
    float* mb = MvOut + (long)b * MV_PER_B;
    float* rb = RK + (long)b * Nn * 400;

    for (int t = 0; t < Nn; t++) {
        if (threadIdx.x < Mm) ws[threadIdx.x] = wb[t * Mm + threadIdx.x];
        __syncthreads();
        if (active) {
            float ed = eb[t * Dd + d];
            float ad = ab[t * Dd + d];
            float* mp = mb + (long)t * (Mm * Dd) + d;
            float rd = 0.f;
            #pragma unroll
            for (int s = 0; s < Mm; s++) {
                float m_ = mv[s];
                mp[s * Dd] = m_;               // Mv_pre emit
                float wv = ws[s];
                rd += wv * m_;                 // read einsum
                mv[s] = m_ + wv * (ad - ed * m_);
            }
            rb[t * 400 + d] = rd;
        }
        __syncthreads();
    }
    if (active) {
        float* mp = mb + (long)Nn * (Mm * Dd) + d;
        #pragma unroll
        for (int s = 0; s < Mm; s++) mp[s * Dd] = mv[s];
    }
}

// ---------------- final projection p = sigmoid([f | f_l] . Wp + bp) ----------------
__global__ void p_kernel(const float* __restrict__ f, const float* __restrict__ fl,
                         const float* __restrict__ Wp, const float* __restrict__ bp,
                         float* __restrict__ outp)
{
    int b = blockIdx.x;
    __shared__ float wsh[400];
    for (int i = threadIdx.x; i < 400; i += blockDim.x) wsh[i] = Wp[i];
    __syncthreads();
    int t = threadIdx.x;
    if (t < Nn) {
        float acc = bp[0];
        const float* flb = fl + (long)b * Nn * Dd;
        for (int i = 0; i < Nn; i++)          // coalesced across threads t
            acc += flb[(long)i * Dd + t] * wsh[200 + i];
        const float* fb = f + ((long)b * Nn + t) * Dd;
        for (int d = 0; d < Dd; d++)
            acc += fb[d] * wsh[d];
        outp[b * Nn + t] = 1.f / (1.f + expf(-acc));
    }
}

// ---------------- host ----------------
extern "C" void kernel_launch(void* const* d_in, const int* in_sizes, int n_in,
                              void* d_out, int out_size)
{
    const int*   q      = (const int*)  d_in[0];
    const int*   r      = (const int*)  d_in[1];
    const float* bert   = (const float*)d_in[2];
    const float* k_emb  = (const float*)d_in[3];
    const float* v_emb  = (const float*)d_in[4];
    const float* Mk     = (const float*)d_in[5];
    const float* Mv0    = (const float*)d_in[6];
    const float* W_at   = (const float*)d_in[7];
    const float* b_at   = (const float*)d_in[8];
    const float* W_at2  = (const float*)d_in[9];
    const float* b_at2  = (const float*)d_in[10];
    const float* W_fus  = (const float*)d_in[11];
    const float* b_fus  = (const float*)d_in[12];
    const float* W_e    = (const float*)d_in[13];
    const float* b_e    = (const float*)d_in[14];
    const float* W_a    = (const float*)d_in[15];
    const float* b_a    = (const float*)d_in[16];
    const float* W_f    = (const float*)d_in[17];
    const float* b_f    = (const float*)d_in[18];
    const float* W_p    = (const float*)d_in[19];
    const float* b_p    = (const float*)d_in[20];

    float* outp  = (float*)d_out;
    float* outMv = outp + OUT_P_SIZE;
    float* outw  = outMv + OUT_MV_SIZE;

    float *em, *VE, *RK, *e_s, *a_s, *f_s, *fl_s, *wlog;
    cudaGetSymbolAddress((void**)&em,   g_em);
    cudaGetSymbolAddress((void**)&VE,   g_VE);
    cudaGetSymbolAddress((void**)&RK,   g_RK);
    cudaGetSymbolAddress((void**)&e_s,  g_e);
    cudaGetSymbolAddress((void**)&a_s,  g_a);
    cudaGetSymbolAddress((void**)&f_s,  g_f);
    cudaGetSymbolAddress((void**)&fl_s, g_fl);
    cudaGetSymbolAddress((void**)&wlog, g_wlog);

    // 1. gather k,v into concat buffers
    gather_kernel<<<BT, 64>>>(q, r, k_emb, v_emb, RK, VE);

    // 2. em = bert @ W_at.T + b_at       [32768,768] x [200,768]
    gemm2<0,false><<<dim3(4, 256, 1), 256>>>(
        bert, W_at, b_at, em, Bsz*Lb, Dd, Hb, 0, 0, Hb, 1, Dd);

    // 3. em_at[b] = em[b]^T @ W_at2.T + b_at2  -> VE[...,200:400]   (batched, A transposed)
    gemm2<0,true><<<dim3(4, 2, Bsz), 256>>>(
        em, W_at2, b_at2, VE + 200, Dd, Dd, Lb,
        (long)Lb * Dd, (long)Nn * 400, 1, Dd, 400);

    // 4. w logits = k @ Mk.T   [12800,200] x [50,200]
    gemm2<0,false><<<dim3(1, 100, 1), 256>>>(
        RK + 200, Mk, (const float*)nullptr, wlog, BT, Mm, Dd, 0, 0, 400, 1, Mm);

    // 5. softmax -> w output
    softmax50_kernel<<<100, 128>>>(wlog, outw);

    // 6/7. e = sigmoid(v@W_e.T+b), a = tanh(v@W_a.T+b)
    gemm2<1,false><<<dim3(4, 100, 1), 256>>>(
        VE, W_e, b_e, e_s, BT, Dd, Dd, 0, 0, 400, 1, Dd);
    gemm2<2,false><<<dim3(4, 100, 1), 256>>>(
        VE, W_a, b_a, a_s, BT, Dd, Dd, 0, 0, 400, 1, Dd);

    // 8. memory scan: Mv output + read -> RK[...,0:200]
    scan_kernel<<<dim3(Bsz, 4, 1), 64>>>(outw, e_s, a_s, Mv0, outMv, RK);

    // 9. f = tanh([read|k] @ W_f.T + b_f)
    gemm2<2,false><<<dim3(4, 100, 1), 256>>>(
        RK, W_f, b_f, f_s, BT, Dd, 400, 0, 0, 400, 1, Dd);

    // 10. f_l_pre = relu([v|em_at] @ W_fus.T + b_fus)
    gemm2<3,false><<<dim3(4, 100, 1), 256>>>(
        VE, W_fus, b_fus, fl_s, BT, Dd, 400, 0, 0, 400, 1, Dd);

    // 11. p
    p_kernel<<<Bsz, 256>>>(f_s, fl_s, W_p, b_p, outp);
}

// round 4
// speedup vs baseline: 1.7264x; 1.2574x over previous
#include <cuda_runtime.h>
#include <cuda_bf16.h>
#include <math.h>
#include <stdint.h>

// ---------------- problem constants ----------------
#define Bsz   64
#define Nn    200      // seq len == state dim
#define Dd    200
#define Mm    50
#define Lb    512
#define Hb    768
#define NUMQ  10000
#define BT    (Bsz*Nn)          // 12800
#define MV_PER_B 2010000L       // 201*50*200
#define OUT_P_SIZE   12800L
#define OUT_MV_SIZE  128640000L
#define OUT_W_SIZE   640000L

typedef unsigned long long ull;

// ---------------- scratch (static device globals; no runtime alloc) ----------------
__device__ float g_em  [ (long)Bsz*Lb*Dd ];   // [64,512,200]  em = bert@W_at.T+b
__device__ float g_VE  [ (long)BT*400 ];      // [b,n, 0:200]=v, [200:400]=em_at row
__device__ float g_RK  [ (long)BT*400 ];      // [b,n, 0:200]=read, [200:400]=k
__device__ float g_e   [ (long)BT*Dd ];
__device__ float g_a   [ (long)BT*Dd ];
__device__ float g_f   [ (long)BT*Dd ];
__device__ float g_fl  [ (long)BT*Dd ];       // f_l_pre [b, i, j] row-major
__device__ float g_wlog[ (long)BT*Mm ];

// ---------------- packed f32x2 helpers (fp32 path for Mv/w-critical GEMMs) ----------------
__device__ __forceinline__ ull dup2(float x) {
    ull r; asm("mov.b64 %0, {%1, %1};" : "=l"(r) : "f"(x)); return r;
}
__device__ __forceinline__ void fma2(ull& d, ull a, ull b) {
    asm("fma.rn.f32x2 %0, %1, %2, %0;" : "+l"(d) : "l"(a), "l"(b));
}
__device__ __forceinline__ float2 unpk2(ull v) {
    float2 f; asm("mov.b64 {%0, %1}, %2;" : "=f"(f.x), "=f"(f.y) : "l"(v)); return f;
}

// ---------------- bf16 MMA helpers ----------------
__device__ __forceinline__ uint32_t cvt2(float lo, float hi) {
    uint32_t r; asm("cvt.rn.bf16x2.f32 %0, %1, %2;" : "=r"(r) : "f"(hi), "f"(lo)); return r;
}
__device__ __forceinline__ uint32_t smem_u32(const void* p) {
    return (uint32_t)__cvta_generic_to_shared(p);
}
__device__ __forceinline__ void ldsm_x4(uint32_t& r0, uint32_t& r1, uint32_t& r2, uint32_t& r3,
                                        uint32_t addr) {
    asm volatile("ldmatrix.sync.aligned.m8n8.x4.shared.b16 {%0,%1,%2,%3}, [%4];"
                 : "=r"(r0), "=r"(r1), "=r"(r2), "=r"(r3) : "r"(addr));
}
__device__ __forceinline__ void mma16816(float* c, const uint32_t* a, const uint32_t* b) {
    asm volatile("mma.sync.aligned.m16n8k16.row.col.f32.bf16.bf16.f32 "
                 "{%0,%1,%2,%3}, {%4,%5,%6,%7}, {%8,%9}, {%0,%1,%2,%3};"
                 : "+f"(c[0]), "+f"(c[1]), "+f"(c[2]), "+f"(c[3])
                 : "r"(a[0]), "r"(a[1]), "r"(a[2]), "r"(a[3]), "r"(b[0]), "r"(b[1]));
}

template<int ACT>
__device__ __forceinline__ float act_f(float v) {
    if (ACT == 1) return 1.f / (1.f + expf(-v));
    if (ACT == 2) return tanhf(v);
    if (ACT == 3) return fmaxf(v, 0.f);
    return v;
}

// ---------------- bf16 tensor-core GEMM: C = act(A @ B^T + bias) ----------------
// fp32 in/out; converts to bf16 on the smem-fill path. fp32 accumulate.
// Block tile 128M x 64N, BK=32, 256 threads (8 warps: 4M x 2N, warp tile 32x32).
// A[m,k] = A[m*lda_row + k*lda_k]; B is [N,K] row-major.
// Only used for GEMMs that feed p (precision non-critical for global rel_err).
template<int ACT, bool TRANS_A>
__global__ __launch_bounds__(256)
void mma_gemm(const float* __restrict__ A, const float* __restrict__ B,
              const float* __restrict__ bias, float* __restrict__ C,
              int M, int N, int K, long sAb, long sCb,
              int lda_row, int lda_k, int ldc)
{
    __shared__ __align__(16) __nv_bfloat16 As[128][40];  // 32 K + 8 pad (80B rows)
    __shared__ __align__(16) __nv_bfloat16 Bs[64][40];
    A += (long)blockIdx.z * sAb;
    C += (long)blockIdx.z * sCb;
    const int tid  = threadIdx.x;
    const int lane = tid & 31, warp = tid >> 5;
    const int wm = (warp >> 1) * 32, wn = (warp & 1) * 32;
    const int m0 = blockIdx.y * 128, n0 = blockIdx.x * 64;

    float c[2][4][4] = {};

    const uint32_t as_base = smem_u32(&As[0][0]);
    const uint32_t bs_base = smem_u32(&Bs[0][0]);
    // A ldmatrix addrs: quad (rows0-7,k0-7)->a0, (rows8-15,k0-7)->a1, (rows0-7,k8-15)->a2, ...
    const uint32_t a_addr0 = as_base + (uint32_t)(wm + (lane & 15)) * 80u + (uint32_t)(lane >> 4) * 16u;
    // B ldmatrix addrs (no trans: B stored [n][k] = col-major K x N as mma wants):
    // regs: {b0(nt even), b1(nt even), b0(nt odd), b1(nt odd)}
    const uint32_t b_addr0 = bs_base + (uint32_t)(wn + (lane >> 4) * 8 + (lane & 7)) * 80u
                           + (uint32_t)((lane >> 3) & 1) * 16u;

    for (int k0 = 0; k0 < K; k0 += 32) {
        // ---- fill As (128x32), fp32 -> bf16 ----
        if (!TRANS_A) {
            #pragma unroll
            for (int u = 0; u < 4; u++) {
                int slot = tid + u * 256;            // 1024 float4 slots
                int row = slot >> 3, kq = (slot & 7) * 4;
                int m = m0 + row;
                float4 v = make_float4(0.f, 0.f, 0.f, 0.f);
                if (m < M) {
                    int k = k0 + kq;
                    if (k + 3 < K) v = *(const float4*)&A[(long)m * lda_row + k];
                    else {
                        float t0 = (k     < K) ? A[(long)m * lda_row + k    ] : 0.f;
                        float t1 = (k + 1 < K) ? A[(long)m * lda_row + k + 1] : 0.f;
                        float t2 = (k + 2 < K) ? A[(long)m * lda_row + k + 2] : 0.f;
                        float t3 = (k + 3 < K) ? A[(long)m * lda_row + k + 3] : 0.f;
                        v = make_float4(t0, t1, t2, t3);
                    }
                }
                uint2 pk; pk.x = cvt2(v.x, v.y); pk.y = cvt2(v.z, v.w);
                *(uint2*)&As[row][kq] = pk;
            }
        } else {
            #pragma unroll
            for (int u = 0; u < 16; u++) {
                int idx = tid + u * 256;             // 4096 scalars, m contiguous
                int mm = idx & 127, kk = idx >> 7;
                int m = m0 + mm, k = k0 + kk;
                float v = (m < M && k < K) ? A[(long)m * lda_row + (long)k * lda_k] : 0.f;
                As[mm][kk] = __float2bfloat16(v);
            }
        }
        // ---- fill Bs (64x32) ----
        #pragma unroll
        for (int u = 0; u < 2; u++) {
            int slot = tid + u * 256;                // 512 float4 slots
            int row = slot >> 3, kq = (slot & 7) * 4;
            int n = n0 + row;
            float4 v = make_float4(0.f, 0.f, 0.f, 0.f);
            if (n < N) {
                int k = k0 + kq;
                if (k + 3 < K) v = *(const float4*)&B[(long)n * K + k];
                else {
                    float t0 = (k     < K) ? B[(long)n * K + k    ] : 0.f;
                    float t1 = (k + 1 < K) ? B[(long)n * K + k + 1] : 0.f;
                    float t2 = (k + 2 < K) ? B[(long)n * K + k + 2] : 0.f;
                    float t3 = (k + 3 < K) ? B[(long)n * K + k + 3] : 0.f;
                    v = make_float4(t0, t1, t2, t3);
                }
            }
            uint2 pk; pk.x = cvt2(v.x, v.y); pk.y = cvt2(v.z, v.w);
            *(uint2*)&Bs[row][kq] = pk;
        }
        __syncthreads();
        // ---- 2 x k16 MMA steps ----
        #pragma unroll
        for (int ks = 0; ks < 2; ks++) {
            uint32_t a[2][4], b[2][4];
            ldsm_x4(a[0][0], a[0][1], a[0][2], a[0][3], a_addr0 + ks * 32u);
            ldsm_x4(a[1][0], a[1][1], a[1][2], a[1][3], a_addr0 + 16u * 80u + ks * 32u);
            ldsm_x4(b[0][0], b[0][1], b[0][2], b[0][3], b_addr0 + ks * 32u);
            ldsm_x4(b[1][0], b[1][1], b[1][2], b[1][3], b_addr0 + 16u * 80u + ks * 32u);
            #pragma unroll
            for (int mt = 0; mt < 2; mt++) {
                mma16816(c[mt][0], a[mt], &b[0][0]);
                mma16816(c[mt][1], a[mt], &b[0][2]);
                mma16816(c[mt][2], a[mt], &b[1][0]);
                mma16816(c[mt][3], a[mt], &b[1][2]);
            }
        }
        __syncthreads();
    }
    // ---- epilogue ----
    #pragma unroll
    for (int mt = 0; mt < 2; mt++) {
        int r0 = m0 + wm + mt * 16 + (lane >> 2);
        #pragma unroll
        for (int nt = 0; nt < 4; nt++) {
            int col = n0 + wn + nt * 8 + (lane & 3) * 2;
            if (col >= N) continue;
            float bb0 = bias ? bias[col] : 0.f;
            bool c1ok = (col + 1 < N);
            float bb1 = c1ok ? (bias ? bias[col + 1] : 0.f) : 0.f;
            if (r0 < M) {
                C[(long)r0 * ldc + col] = act_f<ACT>(c[mt][nt][0] + bb0);
                if (c1ok) C[(long)r0 * ldc + col + 1] = act_f<ACT>(c[mt][nt][1] + bb1);
            }
            if (r0 + 8 < M) {
                C[(long)(r0 + 8) * ldc + col] = act_f<ACT>(c[mt][nt][2] + bb0);
                if (c1ok) C[(long)(r0 + 8) * ldc + col + 1] = act_f<ACT>(c[mt][nt][3] + bb1);
            }
        }
    }
}

// ---------------- fp32 f32x2 GEMM (Mv/w-critical path: wlog, e, a) ----------------
template<int ACT, bool TRANS_A>
__global__ __launch_bounds__(256)
void gemm2(const float* __restrict__ A, const float* __restrict__ B,
           const float* __restrict__ bias, float* __restrict__ C,
           int M, int N, int K, long sAb, long sCb,
           int lda_row, int lda_k, int ldc)
{
    __shared__ float As[16][128];   // [k][m]
    __shared__ float Bs[16][64];    // [k][n]
    A += (long)blockIdx.z * sAb;
    C += (long)blockIdx.z * sCb;
    const int tid = threadIdx.x;
    const int tx = tid & 15;
    const int ty = tid >> 4;
    const int m0 = blockIdx.y * 128, n0 = blockIdx.x * 64;

    ull acc[4][4] = {};

    for (int k0 = 0; k0 < K; k0 += 16) {
        const bool ktail = (k0 + 16 > K);
        #pragma unroll
        for (int u = 0; u < 2; u++) {
            int f4  = tid + u * 256;
            int row = f4 >> 2, kq = (f4 & 3) * 4;
            int m = m0 + row;
            float4 v = make_float4(0.f, 0.f, 0.f, 0.f);
            if (m < M) {
                if (!ktail) {
                    v = *(const float4*)&A[(long)m * lda_row + k0 + kq];
                } else {
                    float t4[4];
                    #pragma unroll
                    for (int j = 0; j < 4; j++) {
                        int k = k0 + kq + j;
                        t4[j] = (k < K) ? A[(long)m * lda_row + k] : 0.f;
                    }
                    v = make_float4(t4[0], t4[1], t4[2], t4[3]);
                }
            }
            As[kq + 0][row] = v.x; As[kq + 1][row] = v.y;
            As[kq + 2][row] = v.z; As[kq + 3][row] = v.w;
        }
        {
            int n = tid >> 2, kq = (tid & 3) * 4;
            int nn = n0 + n;
            float4 v = make_float4(0.f, 0.f, 0.f, 0.f);
            if (nn < N) {
                if (!ktail) {
                    v = *(const float4*)&B[(long)nn * K + k0 + kq];
                } else {
                    float t4[4];
                    #pragma unroll
                    for (int j = 0; j < 4; j++) {
                        int k = k0 + kq + j;
                        t4[j] = (k < K) ? B[(long)nn * K + k] : 0.f;
                    }
                    v = make_float4(t4[0], t4[1], t4[2], t4[3]);
                }
            }
            Bs[kq + 0][n] = v.x; Bs[kq + 1][n] = v.y;
            Bs[kq + 2][n] = v.z; Bs[kq + 3][n] = v.w;
        }
        __syncthreads();
        #pragma unroll
        for (int k = 0; k < 16; k++) {
            const ull* ap = (const ull*)&As[k][ty * 8];
            ull a0 = ap[0], a1 = ap[1], a2 = ap[2], a3 = ap[3];
            float4 bv = *(const float4*)&Bs[k][tx * 4];
            ull b0 = dup2(bv.x), b1 = dup2(bv.y), b2 = dup2(bv.z), b3 = dup2(bv.w);
            fma2(acc[0][0], a0, b0); fma2(acc[0][1], a0, b1);
            fma2(acc[0][2], a0, b2); fma2(acc[0][3], a0, b3);
            fma2(acc[1][0], a1, b0); fma2(acc[1][1], a1, b1);
            fma2(acc[1][2], a1, b2); fma2(acc[1][3], a1, b3);
            fma2(acc[2][0], a2, b0); fma2(acc[2][1], a2, b1);
            fma2(acc[2][2], a2, b2); fma2(acc[2][3], a2, b3);
            fma2(acc[3][0], a3, b0); fma2(acc[3][1], a3, b1);
            fma2(acc[3][2], a3, b2); fma2(acc[3][3], a3, b3);
        }
        __syncthreads();
    }
    #pragma unroll
    for (int mp = 0; mp < 4; mp++) {
        int m = m0 + ty * 8 + mp * 2;
        #pragma unroll
        for (int j = 0; j < 4; j++) {
            int n = n0 + tx * 4 + j;
            if (n >= N) continue;
            float2 c2 = unpk2(acc[mp][j]);
            float bb = bias ? bias[n] : 0.f;
            float v0 = act_f<ACT>(c2.x + bb), v1 = act_f<ACT>(c2.y + bb);
            if (m     < M) C[(long)(m    ) * ldc + n] = v0;
            if (m + 1 < M) C[(long)(m + 1) * ldc + n] = v1;
        }
    }
}

// ---------------- embedding gather (vectorized float4) ----------------
__global__ void gather_kernel(const int* __restrict__ q, const int* __restrict__ r,
                              const float* __restrict__ k_emb, const float* __restrict__ v_emb,
                              float* __restrict__ RK, float* __restrict__ VE)
{
    int bt = blockIdx.x;
    int j  = threadIdx.x;
    if (j >= 50) return;
    int qv = q[bt];
    int xv = qv + NUMQ * r[bt];
    float4 kv = ((const float4*)(k_emb + (long)qv * Dd))[j];
    float4 vv = ((const float4*)(v_emb + (long)xv * Dd))[j];
    ((float4*)(RK + (long)bt * 400 + 200))[j] = kv;
    ((float4*)(VE + (long)bt * 400))[j]       = vv;
}

// ---------------- row softmax over 50 ----------------
__global__ void softmax50_kernel(const float* __restrict__ lg, float* __restrict__ wout)
{
    int row = blockIdx.x * blockDim.x + threadIdx.x;
    if (row >= BT) return;
    const float* x = lg + (long)row * Mm;
    float e[Mm];
    float mx = -3.4e38f;
    #pragma unroll
    for (int s = 0; s < Mm; s++) { e[s] = x[s]; mx = fmaxf(mx, e[s]); }
    float sum = 0.f;
    #pragma unroll
    for (int s = 0; s < Mm; s++) { e[s] = expf(e[s] - mx); sum += e[s]; }
    float inv = 1.f / sum;
    float* o = wout + (long)row * Mm;
    #pragma unroll
    for (int s = 0; s < Mm; s++) o[s] = e[s] * inv;
}

// ---------------- memory scan: Mv recurrence + read einsum ----------------
__global__ void scan_kernel(const float* __restrict__ w, const float* __restrict__ e,
                            const float* __restrict__ a, const float* __restrict__ Mv0,
                            float* __restrict__ MvOut, float* __restrict__ RK)
{
    int b = blockIdx.x;
    int d = blockIdx.y * 50 + threadIdx.x;
    bool active = (threadIdx.x < 50);
    __shared__ float ws[Mm];
    float mv[Mm];
    if (active) {
        #pragma unroll
        for (int s = 0; s < Mm; s++) mv[s] = Mv0[s * Dd + d];
    }
    const float* wb = w + (long)b * Nn * Mm;
    const float* eb = e + (long)b * Nn * Dd;
    const float* ab = a + (long)b * Nn * Dd;
    float* mb = MvOut + (long)b * MV_PER_B;
    float* rb = RK + (long)b * Nn * 400;

    for (int t = 0; t < Nn; t++) {
        if (threadIdx.x < Mm) ws[threadIdx.x] = wb[t * Mm + threadIdx.x];
        __syncthreads();
        if (active) {
            float ed = eb[t * Dd + d];
            float ad = ab[t * Dd + d];
            float* mp = mb + (long)t * (Mm * Dd) + d;
            float rd = 0.f;
            #pragma unroll
            for (int s = 0; s < Mm; s++) {
                float m_ = mv[s];
                mp[s * Dd] = m_;
                float wv = ws[s];
                rd += wv * m_;
                mv[s] = m_ + wv * (ad - ed * m_);
            }
            rb[t * 400 + d] = rd;
        }
        __syncthreads();
    }
    if (active) {
        float* mp = mb + (long)Nn * (Mm * Dd) + d;
        #pragma unroll
        for (int s = 0; s < Mm; s++) mp[s * Dd] = mv[s];
    }
}

// ---------------- final projection p = sigmoid([f | f_l] . Wp + bp) ----------------
__global__ void p_kernel(const float* __restrict__ f, const float* __restrict__ fl,
                         const float* __restrict__ Wp, const float* __restrict__ bp,
                         float* __restrict__ outp)
{
    int b = blockIdx.x;
    __shared__ float wsh[400];
    for (int i = threadIdx.x; i < 400; i += blockDim.x) wsh[i] = Wp[i];
    __syncthreads();
    int t = blockIdx.y * 128 + threadIdx.x;
    if (t < Nn) {
        float acc = bp[0];
        const float* flb = fl + (long)b * Nn * Dd;
        #pragma unroll 4
        for (int i = 0; i < Nn; i++)
            acc += flb[(long)i * Dd + t] * wsh[200 + i];
        const float4* fb = (const float4*)(f + ((long)b * Nn + t) * Dd);
        #pragma unroll 5
        for (int dq = 0; dq < 50; dq++) {
            float4 v = fb[dq];
            acc += v.x * wsh[dq*4] + v.y * wsh[dq*4+1] + v.z * wsh[dq*4+2] + v.w * wsh[dq*4+3];
        }
        outp[b * Nn + t] = 1.f / (1.f + expf(-acc));
    }
}

// ---------------- host ----------------
extern "C" void kernel_launch(void* const* d_in, const int* in_sizes, int n_in,
                              void* d_out, int out_size)
{
    const int*   q      = (const int*)  d_in[0];
    const int*   r      = (const int*)  d_in[1];
    const float* bert   = (const float*)d_in[2];
    const float* k_emb  = (const float*)d_in[3];
    const float* v_emb  = (const float*)d_in[4];
    const float* Mk     = (const float*)d_in[5];
    const float* Mv0    = (const float*)d_in[6];
    const float* W_at   = (const float*)d_in[7];
    const float* b_at   = (const float*)d_in[8];
    const float* W_at2  = (const float*)d_in[9];
    const float* b_at2  = (const float*)d_in[10];
    const float* W_fus  = (const float*)d_in[11];
    const float* b_fus  = (const float*)d_in[12];
    const float* W_e    = (const float*)d_in[13];
    const float* b_e    = (const float*)d_in[14];
    const float* W_a    = (const float*)d_in[15];
    const float* b_a    = (const float*)d_in[16];
    const float* W_f    = (const float*)d_in[17];
    const float* b_f    = (const float*)d_in[18];
    const float* W_p    = (const float*)d_in[19];
    const float* b_p    = (const float*)d_in[20];

    float* outp  = (float*)d_out;
    float* outMv = outp + OUT_P_SIZE;
    float* outw  = outMv + OUT_MV_SIZE;

    float *em, *VE, *RK, *e_s, *a_s, *f_s, *fl_s, *wlog;
    cudaGetSymbolAddress((void**)&em,   g_em);
    cudaGetSymbolAddress((void**)&VE,   g_VE);
    cudaGetSymbolAddress((void**)&RK,   g_RK);
    cudaGetSymbolAddress((void**)&e_s,  g_e);
    cudaGetSymbolAddress((void**)&a_s,  g_a);
    cudaGetSymbolAddress((void**)&f_s,  g_f);
    cudaGetSymbolAddress((void**)&fl_s, g_fl);
    cudaGetSymbolAddress((void**)&wlog, g_wlog);

    // 1. gather k,v into concat buffers
    gather_kernel<<<BT, 64>>>(q, r, k_emb, v_emb, RK, VE);

    // 2. em = bert @ W_at.T + b_at   [32768,768]x[200,768]   (bf16 MMA; p-path only)
    mma_gemm<0,false><<<dim3(4, 256, 1), 256>>>(
        bert, W_at, b_at, em, Bsz*Lb, Dd, Hb, 0, 0, Hb, 1, Dd);

    // 3. em_at[b] = em[b]^T @ W_at2.T + b_at2 -> VE[...,200:400]  (bf16 MMA, TRANS_A)
    mma_gemm<0,true><<<dim3(4, 2, Bsz), 256>>>(
        em, W_at2, b_at2, VE + 200, Dd, Dd, Lb,
        (long)Lb * Dd, (long)Nn * 400, 1, Dd, 400);

    // 4. w logits = k @ Mk.T  (fp32 — feeds softmax/Mv, precision-critical)
    gemm2<0,false><<<dim3(1, 100, 1), 256>>>(
        RK + 200, Mk, (const float*)nullptr, wlog, BT, Mm, Dd, 0, 0, 400, 1, Mm);

    // 5. softmax -> w output
    softmax50_kernel<<<100, 128>>>(wlog, outw);

    // 6/7. e = sigmoid(v@W_e.T+b), a = tanh(v@W_a.T+b)  (fp32 — feed Mv)
    gemm2<1,false><<<dim3(4, 100, 1), 256>>>(
        VE, W_e, b_e, e_s, BT, Dd, Dd, 0, 0, 400, 1, Dd);
    gemm2<2,false><<<dim3(4, 100, 1), 256>>>(
        VE, W_a, b_a, a_s, BT, Dd, Dd, 0, 0, 400, 1, Dd);

    // 8. memory scan: Mv output + read -> RK[...,0:200]
    scan_kernel<<<dim3(Bsz, 4, 1), 64>>>(outw, e_s, a_s, Mv0, outMv, RK);

    // 9. f = tanh([read|k] @ W_f.T + b_f)   (bf16 MMA; p-path only)
    mma_gemm<2,false><<<dim3(4, 100, 1), 256>>>(
        RK, W_f, b_f, f_s, BT, Dd, 400, 0, 0, 400, 1, Dd);

    // 10. f_l_pre = relu([v|em_at] @ W_fus.T + b_fus)  (bf16 MMA; p-path only)
    mma_gemm<3,false><<<dim3(4, 100, 1), 256>>>(
        VE, W_fus, b_fus, fl_s, BT, Dd, 400, 0, 0, 400, 1, Dd);

    // 11. p
    p_kernel<<<dim3(Bsz, 2, 1), 128>>>(f_s, fl_s, W_p, b_p, outp);
}